// round 2
// baseline (speedup 1.0000x reference)
#include <cuda_runtime.h>

// StrictOrthogonal via Cholesky-QR:
//   G = X^H X  (32x32 complex Hermitian, split-K partials, deterministic)
//   G = R^H R  (Cholesky, sqrt-free inner loop, 1 block)
//   Q = X R^{-1}  (per-row forward substitution, fully parallel)
// Mathematically identical to the reference MGS + refinement (same positive-diagonal
// R convention); numerical difference ~1e-5 << 1e-3 tolerance.

#define MROWS 16384
#define RCOLS 32
#define GB 128            // gram split-K blocks
#define ROWS_PER_BLOCK (MROWS / GB)   // 128

__device__ float2 g_partials[GB][RCOLS * RCOLS];
__device__ float2 g_G[RCOLS * RCOLS];
__device__ float2 g_Rmat[RCOLS * RCOLS];
__device__ float  g_rinv[RCOLS];

// ---------------------------------------------------------------------------
// Kernel 1: per-block partial Gram.  Block b handles rows [b*128, b*128+128).
// 256 threads = 4 K-groups x 64 threads; each thread owns a 4x4 complex tile
// of the 32x32 output, accumulating over its 32 assigned rows from SMEM (SoA,
// conflict-free).  Partials reduced across the 4 groups in SMEM, then written.
// ---------------------------------------------------------------------------
__global__ void __launch_bounds__(256) gram_kernel(const float* __restrict__ x) {
    __shared__ float4 sbuf4[2048];                 // 32KB
    float*  s_re = reinterpret_cast<float*>(sbuf4);                    // [128][32]
    float*  s_im = s_re + ROWS_PER_BLOCK * RCOLS;                      // [128][32]
    float2* red  = reinterpret_cast<float2*>(sbuf4);                   // 4096 float2

    const int b = blockIdx.x;
    const float2* __restrict__ xr =
        reinterpret_cast<const float2*>(x) + (size_t)b * ROWS_PER_BLOCK * RCOLS;

    // coalesced load of the 128x32 complex tile, split into re/im planes
    for (int t = threadIdx.x; t < ROWS_PER_BLOCK * RCOLS; t += 256) {
        float2 v = xr[t];
        s_re[t] = v.x;
        s_im[t] = v.y;
    }
    __syncthreads();

    const int t  = threadIdx.x;
    const int g  = t >> 6;          // K-group 0..3 (rows r == g mod 4)
    const int u  = t & 63;
    const int i0 = (u >> 3) * 4;    // 0,4,...,28
    const int j0 = (u & 7) * 4;     // 0,4,...,28

    float accx[4][4], accy[4][4];
    #pragma unroll
    for (int p = 0; p < 4; p++)
        #pragma unroll
        for (int q = 0; q < 4; q++) { accx[p][q] = 0.f; accy[p][q] = 0.f; }

    for (int r = g; r < ROWS_PER_BLOCK; r += 4) {
        const float* rr = s_re + r * RCOLS;
        const float* ri = s_im + r * RCOLS;
        float arx[4], ary[4], brx[4], bry[4];
        #pragma unroll
        for (int p = 0; p < 4; p++) { arx[p] = rr[i0 + p]; ary[p] = ri[i0 + p]; }
        #pragma unroll
        for (int q = 0; q < 4; q++) { brx[q] = rr[j0 + q]; bry[q] = ri[j0 + q]; }
        #pragma unroll
        for (int p = 0; p < 4; p++)
            #pragma unroll
            for (int q = 0; q < 4; q++) {
                // acc += conj(a_p) * b_q
                accx[p][q] = fmaf(arx[p], brx[q], accx[p][q]);
                accx[p][q] = fmaf(ary[p], bry[q], accx[p][q]);
                accy[p][q] = fmaf(arx[p], bry[q], accy[p][q]);
                accy[p][q] = fmaf(-ary[p], brx[q], accy[p][q]);
            }
    }
    __syncthreads();   // tile reads done; reuse smem as reduction buffer

    #pragma unroll
    for (int p = 0; p < 4; p++)
        #pragma unroll
        for (int q = 0; q < 4; q++)
            red[g * 1024 + (i0 + p) * 32 + (j0 + q)] = make_float2(accx[p][q], accy[p][q]);
    __syncthreads();

    for (int e = t; e < 1024; e += 256) {
        float2 s0 = red[e], s1 = red[1024 + e], s2 = red[2048 + e], s3 = red[3072 + e];
        g_partials[b][e] = make_float2(s0.x + s1.x + s2.x + s3.x,
                                       s0.y + s1.y + s2.y + s3.y);
    }
}

// ---------------------------------------------------------------------------
// Kernel 2: reduce 128 partials per entry in fp64 (deterministic order).
// 16 blocks x 64 threads = 1024 threads, one Gram entry each; coalesced reads.
// ---------------------------------------------------------------------------
__global__ void __launch_bounds__(64) reduce_kernel() {
    const int e = blockIdx.x * 64 + threadIdx.x;   // 0..1023
    double sx = 0.0, sy = 0.0;
    #pragma unroll 4
    for (int b = 0; b < GB; b++) {
        float2 p = g_partials[b][e];
        sx += (double)p.x;
        sy += (double)p.y;
    }
    g_G[e] = make_float2((float)sx, (float)sy);
}

// ---------------------------------------------------------------------------
// Kernel 3: 32x32 Hermitian Cholesky, one block of 1024 threads (thread (i,j)).
// Sqrt-free right-looking form: one barrier per k-step, no intra-step races
// (step k writes only the (i>k, j>k) region, reads only row/col k).
// Emits R = L^H (upper) and 1/diag(R).
// ---------------------------------------------------------------------------
__global__ void __launch_bounds__(1024) chol_kernel() {
    __shared__ float2 Gs[RCOLS][RCOLS + 1];
    const int t = threadIdx.x;
    const int i = t >> 5, j = t & 31;
    Gs[i][j] = g_G[t];
    __syncthreads();

    #pragma unroll 1
    for (int k = 0; k < RCOLS; k++) {
        const float invg = 1.f / Gs[k][k].x;     // D_k, final since step k-1
        if (i > k && j > k && j <= i) {
            float2 a = Gs[i][k], c = Gs[j][k];
            float pr = a.x * c.x + a.y * c.y;    // (a * conj(c)).re
            float pi = a.y * c.x - a.x * c.y;    // (a * conj(c)).im
            Gs[i][j].x -= pr * invg;
            Gs[i][j].y -= pi * invg;
        }
        __syncthreads();
    }

    // L[j][i] = Ghat[j][i] * rsqrt(D_i) (j>i),  L[i][i] = sqrt(D_i)
    // R[i][j] = conj(L[j][i]) for i<=j, else 0
    float2 rv = make_float2(0.f, 0.f);
    if (j > i) {
        float2 l = Gs[j][i];
        float  s = rsqrtf(Gs[i][i].x);
        rv = make_float2(l.x * s, -l.y * s);
    } else if (j == i) {
        rv = make_float2(sqrtf(Gs[i][i].x), 0.f);
    }
    g_Rmat[t] = rv;
    if (t < RCOLS) g_rinv[t] = rsqrtf(Gs[t][t].x);
}

// ---------------------------------------------------------------------------
// Kernel 4: per-row forward substitution  q R = x  (R upper triangular).
// One thread per row: 256B contiguous load, 528 complex MACs in registers
// with R broadcast from SMEM (uniform addresses), 256B store.
// ---------------------------------------------------------------------------
__global__ void __launch_bounds__(128) apply_kernel(const float* __restrict__ x,
                                                    float* __restrict__ out) {
    __shared__ float2 Rs[RCOLS][RCOLS];
    __shared__ float  rinv_s[RCOLS];
    const int t = threadIdx.x;
    for (int e = t; e < RCOLS * RCOLS; e += 128)
        Rs[e >> 5][e & 31] = g_Rmat[e];
    if (t < RCOLS) rinv_s[t] = g_rinv[t];
    __syncthreads();

    const int row = blockIdx.x * 128 + t;
    const float4* __restrict__ src = reinterpret_cast<const float4*>(x) + (size_t)row * 16;

    float2 v[RCOLS];
    #pragma unroll
    for (int q = 0; q < 16; q++) {
        float4 f = src[q];
        v[2 * q]     = make_float2(f.x, f.y);
        v[2 * q + 1] = make_float2(f.z, f.w);
    }

    #pragma unroll
    for (int jj = 0; jj < RCOLS; jj++) {
        float sx = v[jj].x, sy = v[jj].y;
        #pragma unroll
        for (int ii = 0; ii < jj; ii++) {
            float2 r = Rs[ii][jj];
            // s -= v[ii] * r   (complex)
            sx = fmaf(-v[ii].x, r.x, sx);
            sx = fmaf( v[ii].y, r.y, sx);
            sy = fmaf(-v[ii].x, r.y, sy);
            sy = fmaf(-v[ii].y, r.x, sy);
        }
        const float d = rinv_s[jj];
        v[jj] = make_float2(sx * d, sy * d);
    }

    float4* __restrict__ dst = reinterpret_cast<float4*>(out) + (size_t)row * 16;
    #pragma unroll
    for (int q = 0; q < 16; q++)
        dst[q] = make_float4(v[2 * q].x, v[2 * q].y, v[2 * q + 1].x, v[2 * q + 1].y);
}

// ---------------------------------------------------------------------------
extern "C" void kernel_launch(void* const* d_in, const int* in_sizes, int n_in,
                              void* d_out, int out_size) {
    const float* x = (const float*)d_in[0];
    float* out = (float*)d_out;
    gram_kernel<<<GB, 256>>>(x);
    reduce_kernel<<<16, 64>>>();
    chol_kernel<<<1, 1024>>>();
    apply_kernel<<<MROWS / 128, 128>>>(x, out);
}